// round 5
// baseline (speedup 1.0000x reference)
#include <cuda_runtime.h>
#include <cuda_bf16.h>
#include <cstdint>
#include <cstddef>

// ---------------------------------------------------------------------------
// CTC-CRF logZ (bonito): S=1024, NZ=5, N=32, T=2000.
// Forward (t<Tf) and backward (t>=Tf) scans in parallel, grid (32,2);
// logZ = log( alpha_mid . beta_mid ). Exp2-domain, renorm every 8 steps.
// R5: TPB 512 (2 states/thread, 16 warps) for latency hiding; LDS.64 score
// reads, single-LDS.128 backward gather, bf16 exchange planes.
// ---------------------------------------------------------------------------

#define NB   32
#define SS   1024
#define CC   5120
#define TPB  512
#define L2E  1.44269504088896f
#define LN2  0.69314718055995f
#define STAGES 6
#define DIST   5

// smem floats: [0, 6*5120) score stages; [30720, 34816) work (fw: alpha
// 2x1024 f32 = 8KB; bw: 2 x 4 planes x 1024 bf16 = 16KB); [34816,+16) red.
#define WOFF   30720
#define REDOFF (WOFF + 4096)
#define SMEM_BYTES ((REDOFF + 16) * 4)

__device__ __align__(16) float g_mid_a[NB][SS];
__device__ __align__(16) float g_mid_b[NB][SS];
__device__ float g_off[2][NB];

__device__ __forceinline__ float ex2f_(float x) {
    float r; asm("ex2.approx.f32 %0,%1;" : "=f"(r) : "f"(x)); return r;
}
__device__ __forceinline__ float lg2f_(float x) {
    float r; asm("lg2.approx.f32 %0,%1;" : "=f"(r) : "f"(x)); return r;
}
__device__ __forceinline__ float rcpf_(float x) {
    float r; asm("rcp.approx.f32 %0,%1;" : "=f"(r) : "f"(x)); return r;
}
__device__ __forceinline__ uint32_t pack_bf2(float a, float b) {
    __nv_bfloat162 h = __floats2bfloat162_rn(a, b);
    return *reinterpret_cast<uint32_t*>(&h);
}
__device__ __forceinline__ float2 unpack_bf2(uint32_t u) {
    __nv_bfloat162 h = *reinterpret_cast<__nv_bfloat162*>(&u);
    return __bfloat1622float2(h);
}

__device__ __forceinline__ void cp16(uint32_t dst, const void* src) {
    asm volatile("cp.async.cg.shared.global [%0],[%1],16;"
                 :: "r"(dst), "l"(src) : "memory");
}
// 20 KB slab, 1280 16B chunks over 512 threads.
__device__ __forceinline__ void cp_slab(const float* g, float* s, int tid) {
    uint32_t db = (uint32_t)__cvta_generic_to_shared(s);
    const char* sb = (const char*)g;
    cp16(db + (uint32_t)tid * 16u, sb + (size_t)tid * 16);
    cp16(db + (uint32_t)(tid + 512) * 16u, sb + (size_t)(tid + 512) * 16);
    if (tid < 256)
        cp16(db + (uint32_t)(tid + 1024) * 16u, sb + (size_t)(tid + 1024) * 16);
}
__device__ __forceinline__ void cp_commit() {
    asm volatile("cp.async.commit_group;" ::: "memory");
}
__device__ __forceinline__ void cp_wait3() {
    asm volatile("cp.async.wait_group 3;" ::: "memory");
}
__device__ __forceinline__ float wmaxf_(float m) {
#pragma unroll
    for (int o = 16; o; o >>= 1)
        m = fmaxf(m, __shfl_xor_sync(0xffffffffu, m, o));
    return m;
}
__device__ __forceinline__ float redmax_(const volatile float* red) {
    float mv = red[0];
#pragma unroll
    for (int k = 1; k < 16; k++) mv = fmaxf(mv, red[k]);
    return mv;
}

// 10 weights (2 states x 5 channels) via 5 conflict-free LDS.64.
#define LOADW(W, sbase) do {                                                   \
    const float2* p_ = (const float2*)((const char*)(sbase) + 40u * tid);      \
    float2 e0_ = p_[0], e1_ = p_[1], e2_ = p_[2], e3_ = p_[3], e4_ = p_[4];    \
    W[0] = ex2f_(e0_.x * L2E); W[1] = ex2f_(e0_.y * L2E);                      \
    W[2] = ex2f_(e1_.x * L2E); W[3] = ex2f_(e1_.y * L2E);                      \
    W[4] = ex2f_(e2_.x * L2E); W[5] = ex2f_(e2_.y * L2E);                      \
    W[6] = ex2f_(e3_.x * L2E); W[7] = ex2f_(e3_.y * L2E);                      \
    W[8] = ex2f_(e4_.x * L2E); W[9] = ex2f_(e4_.y * L2E);                      \
} while (0)

#define ISSUE(IDX) do {                                                        \
    int j_ = (IDX);                                                            \
    if (j_ < steps) {                                                          \
        int t_ = dir ? (T - 1 - j_) : j_;                                      \
        cp_slab(sc + ((size_t)t_ * NB + n) * CC, sm + (j_ % STAGES) * CC, tid);\
    }                                                                          \
    cp_commit();                                                               \
} while (0)

// ---- forward: thread v owns states 2v,2v+1; preds (v>>1)+256r shared ----
#define FWSTEP(I, WC, WN) do {                                                 \
    int i_ = (I);                                                              \
    ISSUE(i_ + DIST);                                                          \
    cp_wait3();                                                                \
    const float* ac_ = al + (i_ & 1) * SS;                                     \
    int pv_ = tid >> 1;                                                        \
    float g0_ = ac_[pv_], g1_ = ac_[pv_ + 256], g2_ = ac_[pv_ + 512], g3_ = ac_[pv_ + 768]; \
    if ((i_ & 7) == 0 && i_) {                                                 \
        float mv_ = redmax_(red); float s_ = rcpf_(mv_); off += lg2f_(mv_);    \
        a0 *= s_; a1 *= s_; g0_ *= s_; g1_ *= s_; g2_ *= s_; g3_ *= s_;        \
    }                                                                          \
    float n0_ = fmaf(WC[1], g0_, WC[0] * a0);                                  \
    n0_ = fmaf(WC[2], g1_, n0_); n0_ = fmaf(WC[3], g2_, n0_); n0_ = fmaf(WC[4], g3_, n0_); \
    float n1_ = fmaf(WC[6], g0_, WC[5] * a1);                                  \
    n1_ = fmaf(WC[7], g1_, n1_); n1_ = fmaf(WC[8], g2_, n1_); n1_ = fmaf(WC[9], g3_, n1_); \
    a0 = n0_; a1 = n1_;                                                        \
    ((float2*)(al + ((i_ + 1) & 1) * SS))[tid] = make_float2(n0_, n1_);        \
    if ((i_ & 7) == 7) {                                                       \
        float m_ = wmaxf_(fmaxf(n0_, n1_));                                    \
        if (lane == 0) red[wid] = m_;                                          \
    }                                                                          \
    if (i_ + 1 < steps) { LOADW(WN, sm + ((i_ + 1) % STAGES) * CC); }          \
    __syncthreads();                                                           \
} while (0)

// ---- backward: owner computes c[s][z]=w*b', scatters bf16 planes; state j
// gathers 4 contiguous entries of plane j>>8; both states -> one LDS.128. ----
#define BWSTEP(I, WC, WN) do {                                                 \
    int i_ = (I);                                                              \
    ISSUE(i_ + DIST);                                                          \
    cp_wait3();                                                                \
    char* pb_ = wk + (i_ & 1) * 8192;                                          \
    *(uint32_t*)(pb_ + 0 * 2048 + 4 * tid) = pack_bf2(WC[1] * b0, WC[6] * b1); \
    *(uint32_t*)(pb_ + 1 * 2048 + 4 * tid) = pack_bf2(WC[2] * b0, WC[7] * b1); \
    *(uint32_t*)(pb_ + 2 * 2048 + 4 * tid) = pack_bf2(WC[3] * b0, WC[8] * b1); \
    *(uint32_t*)(pb_ + 3 * 2048 + 4 * tid) = pack_bf2(WC[4] * b0, WC[9] * b1); \
    float st0_ = WC[0] * b0, st1_ = WC[5] * b1;                                \
    if (i_ + 1 < steps) { LOADW(WN, sm + ((i_ + 1) % STAGES) * CC); }          \
    __syncthreads();                                                           \
    float psc_ = 1.0f;                                                         \
    if ((i_ & 7) == 0 && i_) {                                                 \
        float mv_ = redmax_(red); psc_ = rcpf_(mv_); off += lg2f_(mv_);        \
    }                                                                          \
    uint4 A_ = *(const uint4*)(pb_ + (tid >> 7) * 2048 + 16 * (tid & 127));    \
    float2 p_;                                                                 \
    p_ = unpack_bf2(A_.x); float s0_ = p_.x + p_.y;                            \
    p_ = unpack_bf2(A_.y); s0_ += p_.x + p_.y;                                 \
    p_ = unpack_bf2(A_.z); float s1_ = p_.x + p_.y;                            \
    p_ = unpack_bf2(A_.w); s1_ += p_.x + p_.y;                                 \
    b0 = psc_ * (st0_ + s0_); b1 = psc_ * (st1_ + s1_);                        \
    if ((i_ & 7) == 7) {                                                       \
        float m_ = wmaxf_(fmaxf(b0, b1));                                      \
        if (lane == 0) red[wid] = m_;                                          \
    }                                                                          \
} while (0)

__global__ void __launch_bounds__(TPB, 1)
crf_scan(const float* __restrict__ sc, int T, int Tf) {
    extern __shared__ float sm[];
    const int tid  = threadIdx.x;
    const int n    = blockIdx.x;
    const int dir  = blockIdx.y;
    const int wid  = tid >> 5;
    const int lane = tid & 31;
    volatile float* red = sm + REDOFF;
    const int steps = dir ? (T - Tf) : Tf;

#pragma unroll
    for (int p = 0; p < DIST; p++) ISSUE(p);
    cp_wait3();
    __syncthreads();

    float wA[10], wB[10];
    LOADW(wA, sm + 0 * CC);
    float off = 0.0f;

    if (dir == 0) {
        float* al = sm + WOFF;
        float a0 = 1.f, a1 = 1.f;
        ((float2*)al)[tid] = make_float2(1.f, 1.f);
        __syncthreads();

        int i = 0;
        for (; i + 1 < steps; i += 2) { FWSTEP(i, wA, wB); FWSTEP(i + 1, wB, wA); }
        if (i < steps) { FWSTEP(i, wA, wB); }

        float m = wmaxf_(fmaxf(a0, a1));
        if (lane == 0) red[wid] = m;
        __syncthreads();
        float mv = redmax_(red);
        float s = rcpf_(mv);
        off += lg2f_(mv);
        ((float2*)g_mid_a[n])[tid] = make_float2(a0 * s, a1 * s);
        if (tid == 0) g_off[0][n] = off;
    } else {
        char* wk = (char*)(sm + WOFF);
        float b0 = 1.f, b1 = 1.f;

        int i = 0;
        for (; i + 1 < steps; i += 2) { BWSTEP(i, wA, wB); BWSTEP(i + 1, wB, wA); }
        if (i < steps) { BWSTEP(i, wA, wB); }

        float m = wmaxf_(fmaxf(b0, b1));
        if (lane == 0) red[wid] = m;
        __syncthreads();
        float mv = redmax_(red);
        float s = rcpf_(mv);
        off += lg2f_(mv);
        ((float2*)g_mid_b[n])[tid] = make_float2(b0 * s, b1 * s);
        if (tid == 0) g_off[1][n] = off;
    }
}

__global__ void __launch_bounds__(256)
crf_combine(float* __restrict__ out) {
    __shared__ float par[8];
    const int n = blockIdx.x, tid = threadIdx.x;
    float4 a = ((const float4*)g_mid_a[n])[tid];
    float4 b = ((const float4*)g_mid_b[n])[tid];
    float s = a.x * b.x + a.y * b.y + a.z * b.z + a.w * b.w;
#pragma unroll
    for (int o = 16; o; o >>= 1) s += __shfl_xor_sync(0xffffffffu, s, o);
    if ((tid & 31) == 0) par[tid >> 5] = s;
    __syncthreads();
    if (tid == 0) {
        float t = par[0];
#pragma unroll
        for (int k = 1; k < 8; k++) t += par[k];
        out[n] = LN2 * (g_off[0][n] + g_off[1][n] + lg2f_(t));
    }
}

extern "C" void kernel_launch(void* const* d_in, const int* in_sizes, int n_in,
                              void* d_out, int out_size) {
    const float* sc = (const float*)d_in[0];
    int T = in_sizes[0] / (NB * CC);
    int Tf = (int)(((long long)T * 515) / 1000);
    if (Tf < 1) Tf = 1;
    if (Tf > T - 1) Tf = T - 1;

    cudaFuncSetAttribute(crf_scan, cudaFuncAttributeMaxDynamicSharedMemorySize, SMEM_BYTES);
    crf_scan<<<dim3(NB, 2), TPB, SMEM_BYTES>>>(sc, T, Tf);
    crf_combine<<<NB, 256>>>((float*)d_out);
}